// round 16
// baseline (speedup 1.0000x reference)
#include <cuda_runtime.h>
#include <cstdint>

#define HW_ (128*128)
#define NTOT (16*64)
#define HWP (HW_/2)

__device__ uint32_t g_Qh[NTOT * HWP];
__device__ uint32_t g_Ql[NTOT * HWP];
__device__ uint32_t g_Vh[NTOT * HWP];
__device__ uint32_t g_Vl[NTOT * HWP];
__device__ float    g_K [NTOT * HW_];

// ---- bf16x3 helpers ---------------------------------------------------------
__device__ __forceinline__ void mma_bf16(float c[4], const uint32_t a[4],
                                         const uint32_t b0, const uint32_t b1) {
    asm volatile(
        "mma.sync.aligned.m16n8k16.row.col.f32.bf16.bf16.f32 "
        "{%0,%1,%2,%3}, {%4,%5,%6,%7}, {%8,%9}, {%0,%1,%2,%3};"
        : "+f"(c[0]), "+f"(c[1]), "+f"(c[2]), "+f"(c[3])
        : "r"(a[0]), "r"(a[1]), "r"(a[2]), "r"(a[3]), "r"(b0), "r"(b1));
}

__device__ __forceinline__ void bf16x2_split(float x, float y,
                                             uint32_t& hi2, uint32_t& lo2) {
    uint32_t h;
    asm("cvt.rn.bf16x2.f32 %0, %1, %2;" : "=r"(h) : "f"(y), "f"(x));
    float xh = __uint_as_float(h << 16);
    float yh = __uint_as_float(h & 0xffff0000u);
    float xl = x - xh;
    float yl = y - yh;
    hi2 = h;
    asm("cvt.rn.bf16x2.f32 %0, %1, %2;" : "=r"(lo2) : "f"(yl), "f"(xl));
}

__device__ __forceinline__ void ldsm_x4(uint32_t r[4], uint32_t addr) {
    asm volatile(
        "ldmatrix.sync.aligned.m8n8.x4.shared.b16 {%0,%1,%2,%3}, [%4];"
        : "=r"(r[0]), "=r"(r[1]), "=r"(r[2]), "=r"(r[3]) : "r"(addr));
}

// ---------------------------------------------------------------------------
// Kernel 1: fused 1x1-conv projections (R15 winner, unchanged).
// ---------------------------------------------------------------------------
#define LDW  36
#define LDW1 12
#define WHL  (64*LDW*4)
#define W1HL (64*LDW1*4)
#define XHL  (128*LDW*4)
#define EHL  (128*LDW1*4)
#define NTILE 8

__global__ __launch_bounds__(512) void qvk_kernel(
    const float* __restrict__ x, const float* __restrict__ e,
    const float* __restrict__ W1, const float* __restrict__ b1,
    const float* __restrict__ W2, const float* __restrict__ b2,
    const float* __restrict__ W3, const float* __restrict__ b3)
{
    extern __shared__ uint32_t smu[];
    uint32_t* W2h = smu;
    uint32_t* W2l = W2h + 64*LDW;
    uint32_t* W3h = W2l + 64*LDW;
    uint32_t* W3l = W3h + 64*LDW;
    uint32_t* W1h = W3l + 64*LDW;
    uint32_t* W1l = W1h + 64*LDW1;
    uint32_t* Xph = W1l + 64*LDW1;
    uint32_t* Xpl = Xph + 128*LDW;
    uint32_t* Eph = Xpl + 128*LDW;
    uint32_t* Epl = Eph + 128*LDW1;
    float* b1s = (float*)(Epl + 128*LDW1);
    float* b2s = b1s + 64;
    float* b3s = b2s + 64;

    const int tid = threadIdx.x;
    const int b   = blockIdx.y;

    for (int idx = tid; idx < 2048; idx += 512) {
        int o = idx >> 5, p = idx & 31, c = 2*p;
        uint32_t h, l;
        bf16x2_split(W2[o*64 + c], W2[o*64 + c + 1], h, l);
        W2h[o*LDW + p] = h; W2l[o*LDW + p] = l;
        bf16x2_split(W3[o*64 + c], W3[o*64 + c + 1], h, l);
        W3h[o*LDW + p] = h; W3l[o*LDW + p] = l;
    }
    if (tid < 512) {
        int o = tid >> 3, p = tid & 7, c = 2*p;
        uint32_t h, l;
        bf16x2_split(W1[o*16 + c], W1[o*16 + c + 1], h, l);
        W1h[o*LDW1 + p] = h; W1l[o*LDW1 + p] = l;
    }
    if (tid < 64) { b1s[tid] = b1[tid]; b2s[tid] = b2[tid]; b3s[tid] = b3[tid]; }

    const int warp = tid >> 5;
    const int lane = tid & 31;
    const int g4 = lane >> 2;
    const int tg = lane & 3;
    const int wb = warp & 7;
    const int wh = warp >> 3;
    const int p0 = wb*16;
    const int o0 = wh*32;

    const int arow = ((lane >> 3) & 1)*8 + (lane & 7);
    const int acol = (lane >> 4)*4;
    const uint32_t adrW2_0 = (uint32_t)__cvta_generic_to_shared(
        &W2h[(o0 + arow)*LDW + acol]);
    const uint32_t adrW2_1 = (uint32_t)__cvta_generic_to_shared(
        &W2h[(o0 + 16 + arow)*LDW + acol]);
    const uint32_t adrW3_0 = (uint32_t)__cvta_generic_to_shared(
        &W3h[(o0 + arow)*LDW + acol]);
    const uint32_t adrW3_1 = (uint32_t)__cvta_generic_to_shared(
        &W3h[(o0 + 16 + arow)*LDW + acol]);
    const uint32_t adrW1_0 = (uint32_t)__cvta_generic_to_shared(
        &W1h[(o0 + arow)*LDW1 + acol]);
    const uint32_t adrW1_1 = (uint32_t)__cvta_generic_to_shared(
        &W1h[(o0 + 16 + arow)*LDW1 + acol]);
    const int btile = lane >> 3;
    const int brow  = p0 + (btile >> 1)*8 + (lane & 7);
    const int bcol  = (btile & 1)*4;
    const uint32_t adrX = (uint32_t)__cvta_generic_to_shared(
        &Xph[brow*LDW + bcol]);
    const uint32_t adrE = (uint32_t)__cvta_generic_to_shared(
        &Eph[brow*LDW1 + bcol]);

    for (int t = 0; t < NTILE; t++) {
        const int pblk = (blockIdx.x*NTILE + t) * 128;
        const float* xb = x + b*64*HW_ + pblk;
        const float* eb = e + b*16*HW_ + pblk;

        __syncthreads();
        for (int idx = tid; idx < 32*128; idx += 512) {
            int cp = idx >> 7, p = idx & 127;
            uint32_t h, l;
            bf16x2_split(xb[(2*cp)*HW_ + p], xb[(2*cp+1)*HW_ + p], h, l);
            Xph[p*LDW + cp] = h; Xpl[p*LDW + cp] = l;
        }
        for (int idx = tid; idx < 8*128; idx += 512) {
            int cp = idx >> 7, p = idx & 127;
            uint32_t h, l;
            bf16x2_split(eb[(2*cp)*HW_ + p], eb[(2*cp+1)*HW_ + p], h, l);
            Eph[p*LDW1 + cp] = h; Epl[p*LDW1 + cp] = l;
        }
        __syncthreads();

        float accV[2][2][4], accK[2][2][4], accQ[2][2][4];
        #pragma unroll
        for (int mt = 0; mt < 2; mt++) {
            int r = o0 + mt*16 + g4;
            float v0 = b2s[r], v1 = b2s[r+8];
            float k0 = b3s[r], k1 = b3s[r+8];
            float q0 = b1s[r], q1 = b1s[r+8];
            #pragma unroll
            for (int ntl = 0; ntl < 2; ntl++) {
                accV[mt][ntl][0] = v0; accV[mt][ntl][1] = v0;
                accV[mt][ntl][2] = v1; accV[mt][ntl][3] = v1;
                accK[mt][ntl][0] = k0; accK[mt][ntl][1] = k0;
                accK[mt][ntl][2] = k1; accK[mt][ntl][3] = k1;
                accQ[mt][ntl][0] = q0; accQ[mt][ntl][1] = q0;
                accQ[mt][ntl][2] = q1; accQ[mt][ntl][3] = q1;
            }
        }

        #pragma unroll
        for (int ks = 0; ks < 4; ks++) {
            const uint32_t ko = ks*32;
            uint32_t bxh[4], bxl[4];
            ldsm_x4(bxh, adrX + ko);
            ldsm_x4(bxl, adrX + ko + XHL);
            #pragma unroll
            for (int mt = 0; mt < 2; mt++) {
                const uint32_t aw2 = (mt ? adrW2_1 : adrW2_0) + ko;
                const uint32_t aw3 = (mt ? adrW3_1 : adrW3_0) + ko;
                uint32_t a2h[4], a2l[4], a3h[4], a3l[4];
                ldsm_x4(a2h, aw2);
                ldsm_x4(a2l, aw2 + WHL);
                ldsm_x4(a3h, aw3);
                ldsm_x4(a3l, aw3 + WHL);
                mma_bf16(accV[mt][0], a2h, bxh[0], bxh[1]);
                mma_bf16(accV[mt][0], a2l, bxh[0], bxh[1]);
                mma_bf16(accV[mt][0], a2h, bxl[0], bxl[1]);
                mma_bf16(accV[mt][1], a2h, bxh[2], bxh[3]);
                mma_bf16(accV[mt][1], a2l, bxh[2], bxh[3]);
                mma_bf16(accV[mt][1], a2h, bxl[2], bxl[3]);
                mma_bf16(accK[mt][0], a3h, bxh[0], bxh[1]);
                mma_bf16(accK[mt][0], a3l, bxh[0], bxh[1]);
                mma_bf16(accK[mt][0], a3h, bxl[0], bxl[1]);
                mma_bf16(accK[mt][1], a3h, bxh[2], bxh[3]);
                mma_bf16(accK[mt][1], a3l, bxh[2], bxh[3]);
                mma_bf16(accK[mt][1], a3h, bxl[2], bxl[3]);
            }
        }

        {
            uint32_t beh[4], bel[4];
            ldsm_x4(beh, adrE);
            ldsm_x4(bel, adrE + EHL);
            #pragma unroll
            for (int mt = 0; mt < 2; mt++) {
                const uint32_t aw1 = mt ? adrW1_1 : adrW1_0;
                uint32_t a1h[4], a1l[4];
                ldsm_x4(a1h, aw1);
                ldsm_x4(a1l, aw1 + W1HL);
                mma_bf16(accQ[mt][0], a1h, beh[0], beh[1]);
                mma_bf16(accQ[mt][0], a1l, beh[0], beh[1]);
                mma_bf16(accQ[mt][0], a1h, bel[0], bel[1]);
                mma_bf16(accQ[mt][1], a1h, beh[2], beh[3]);
                mma_bf16(accQ[mt][1], a1l, beh[2], beh[3]);
                mma_bf16(accQ[mt][1], a1h, bel[2], bel[3]);
            }
        }

        #pragma unroll
        for (int mt = 0; mt < 2; mt++) {
            int r = o0 + mt*16 + g4;
            #pragma unroll
            for (int ntl = 0; ntl < 2; ntl++) {
                int pc = pblk + p0 + ntl*8 + 2*tg;
                int pq = pc >> 1;
                int n0 = b*64 + r, n1 = n0 + 8;
                uint32_t h, l;
                bf16x2_split(accQ[mt][ntl][0], accQ[mt][ntl][1], h, l);
                g_Qh[n0*HWP + pq] = h; g_Ql[n0*HWP + pq] = l;
                bf16x2_split(accQ[mt][ntl][2], accQ[mt][ntl][3], h, l);
                g_Qh[n1*HWP + pq] = h; g_Ql[n1*HWP + pq] = l;
                bf16x2_split(accV[mt][ntl][0], accV[mt][ntl][1], h, l);
                g_Vh[n0*HWP + pq] = h; g_Vl[n0*HWP + pq] = l;
                bf16x2_split(accV[mt][ntl][2], accV[mt][ntl][3], h, l);
                g_Vh[n1*HWP + pq] = h; g_Vl[n1*HWP + pq] = l;
                *(float2*)&g_K[n0*HW_ + pc] = make_float2(accK[mt][ntl][0], accK[mt][ntl][1]);
                *(float2*)&g_K[n1*HW_ + pc] = make_float2(accK[mt][ntl][2], accK[mt][ntl][3]);
            }
        }
    }
}

// ---------------------------------------------------------------------------
// Kernel 2: per-head attention, SPLIT ROW-HALVES: 2 CTAs per head (512 thr),
// ~106KB smem -> 2 CTAs/SM so staging/softmax of one CTA overlaps compute of
// the other. A-buf [64][LDP] (Qp half -> Pp half); B-buf [128][LDP] (Vp full
// -> Ktp full). Both phases fully LDSM-fed (R14 scheme).
// ---------------------------------------------------------------------------
#define LDP 68
#define AHL (64*LDP*4)    // byte offset Ah->Al
#define BHL (128*LDP*4)   // byte offset Bh->Bl

__global__ __launch_bounds__(512) void attn_kernel(float* __restrict__ out)
{
    extern __shared__ uint32_t smu[];
    uint32_t* Ah = smu;                  // [64][LDP]
    uint32_t* Al = Ah + 64*LDP;
    uint32_t* Bh = Al + 64*LDP;          // [128][LDP]
    uint32_t* Bl = Bh + 128*LDP;
    float* redM = (float*)(Bl + 128*LDP);  // [4][64]
    float* redS = redM + 256;              // [4][64]

    const int tid  = threadIdx.x;
    const int warp = tid >> 5;
    const int lane = tid & 31;
    const int wb   = warp & 3;     // row band within half (4 bands of 16)
    const int wq   = warp >> 2;    // column quarter (0..3)
    const int n    = blockIdx.x >> 1;
    const int rh   = blockIdx.x & 1;       // row half
    const int rbase = rh*64;
    const uint32_t* Qh = g_Qh + n*HWP + rbase*64;
    const uint32_t* Ql = g_Ql + n*HWP + rbase*64;
    const uint32_t* Vh = g_Vh + n*HWP;
    const uint32_t* Vl = g_Vl + n*HWP;
    const float*    K  = g_K  + n*HW_;

    // Stage Qp half rows + Vp full (pure u32 copies)
    for (int idx = tid; idx < 64*64; idx += 512) {
        int r = idx >> 6, c = idx & 63;
        Ah[r*LDP + c] = Qh[idx];
        Al[r*LDP + c] = Ql[idx];
    }
    for (int idx = tid; idx < HWP; idx += 512) {
        int r = idx >> 6, c = idx & 63;
        Bh[r*LDP + c] = Vh[idx];
        Bl[r*LDP + c] = Vl[idx];
    }
    __syncthreads();

    const int g4 = lane >> 2;
    const int tg = lane & 3;
    const int r0 = wb*16 + g4;     // row within half (0..63)
    const int nt0 = wq*4;

    const int rowA = wb*16 + ((lane >> 3) & 1)*8 + (lane & 7);
    const int colA = (lane >> 4)*4;
    const uint32_t adrA =
        (uint32_t)__cvta_generic_to_shared(&Ah[rowA*LDP + colA]);
    const int tile  = lane >> 3;
    const int rowB0 = (nt0 + (tile >> 1))*8 + (lane & 7);
    const int rowB1 = (nt0 + 2 + (tile >> 1))*8 + (lane & 7);
    const int colB  = (tile & 1)*4;
    const uint32_t adrB0 =
        (uint32_t)__cvta_generic_to_shared(&Bh[rowB0*LDP + colB]);
    const uint32_t adrB1 =
        (uint32_t)__cvta_generic_to_shared(&Bh[rowB1*LDP + colB]);

    float acc[4][4];
    #pragma unroll
    for (int j = 0; j < 4; j++)
        #pragma unroll
        for (int i = 0; i < 4; i++) acc[j][i] = 0.0f;

    // ---- Phase A: S = Q @ V^T
    #pragma unroll 2
    for (int k = 0; k < 8; k++) {
        const uint32_t koff = k*32;
        uint32_t ah[4], al[4], b0h[4], b0l[4], b1h[4], b1l[4];
        ldsm_x4(ah, adrA + koff);
        ldsm_x4(al, adrA + koff + AHL);
        ldsm_x4(b0h, adrB0 + koff);
        ldsm_x4(b0l, adrB0 + koff + BHL);
        ldsm_x4(b1h, adrB1 + koff);
        ldsm_x4(b1l, adrB1 + koff + BHL);
        mma_bf16(acc[0], ah, b0h[0], b0h[1]);
        mma_bf16(acc[0], al, b0h[0], b0h[1]);
        mma_bf16(acc[0], ah, b0l[0], b0l[1]);
        mma_bf16(acc[1], ah, b0h[2], b0h[3]);
        mma_bf16(acc[1], al, b0h[2], b0h[3]);
        mma_bf16(acc[1], ah, b0l[2], b0l[3]);
        mma_bf16(acc[2], ah, b1h[0], b1h[1]);
        mma_bf16(acc[2], al, b1h[0], b1h[1]);
        mma_bf16(acc[2], ah, b1l[0], b1l[1]);
        mma_bf16(acc[3], ah, b1h[2], b1h[3]);
        mma_bf16(acc[3], al, b1h[2], b1h[3]);
        mma_bf16(acc[3], ah, b1l[2], b1l[3]);
    }

    // ---- Softmax (4-warp row groups)
    float m1 = -1e30f, m2 = -1e30f;
    #pragma unroll
    for (int j = 0; j < 4; j++) {
        m1 = fmaxf(m1, fmaxf(acc[j][0], acc[j][1]));
        m2 = fmaxf(m2, fmaxf(acc[j][2], acc[j][3]));
    }
    #pragma unroll
    for (int off = 1; off < 4; off <<= 1) {
        m1 = fmaxf(m1, __shfl_xor_sync(0xFFFFFFFFu, m1, off));
        m2 = fmaxf(m2, __shfl_xor_sync(0xFFFFFFFFu, m2, off));
    }
    if (tg == 0) {
        redM[wq*64 + r0]     = m1;
        redM[wq*64 + r0 + 8] = m2;
    }
    __syncthreads();

    const float gm1 = fmaxf(fmaxf(redM[r0],      redM[64 + r0]),
                            fmaxf(redM[128 + r0], redM[192 + r0]));
    const float gm2 = fmaxf(fmaxf(redM[r0+8],      redM[64 + r0+8]),
                            fmaxf(redM[128 + r0+8], redM[192 + r0+8]));

    float s1 = 0.0f, s2 = 0.0f;
    #pragma unroll
    for (int j = 0; j < 4; j++) {
        acc[j][0] = __expf(acc[j][0] - gm1);
        acc[j][1] = __expf(acc[j][1] - gm1);
        acc[j][2] = __expf(acc[j][2] - gm2);
        acc[j][3] = __expf(acc[j][3] - gm2);
        s1 += acc[j][0] + acc[j][1];
        s2 += acc[j][2] + acc[j][3];
    }
    #pragma unroll
    for (int off = 1; off < 4; off <<= 1) {
        s1 += __shfl_xor_sync(0xFFFFFFFFu, s1, off);
        s2 += __shfl_xor_sync(0xFFFFFFFFu, s2, off);
    }
    if (tg == 0) {
        redS[wq*64 + r0]     = s1;
        redS[wq*64 + r0 + 8] = s2;
    }

    // Store P split into A-buf (each thread's acc pair = one g-pair)
    #pragma unroll
    for (int j = 0; j < 4; j++) {
        const int pb = (nt0 + j)*4 + tg;
        uint32_t h, l;
        bf16x2_split(acc[j][0], acc[j][1], h, l);
        Ah[r0*LDP + pb] = h; Al[r0*LDP + pb] = l;
        bf16x2_split(acc[j][2], acc[j][3], h, l);
        Ah[(r0+8)*LDP + pb] = h; Al[(r0+8)*LDP + pb] = l;
    }
    // Stage K transposed + g-pair packed: Ktp[w][gp]
    for (int idx = tid; idx < 64*128; idx += 512) {
        int gp = idx >> 7, w = idx & 127;
        uint32_t h, l;
        bf16x2_split(K[(2*gp)*128 + w], K[(2*gp+1)*128 + w], h, l);
        Bh[w*LDP + gp] = h; Bl[w*LDP + gp] = l;
    }
    __syncthreads();

    const float inv1 = 1.0f / (redS[r0] + redS[64 + r0] +
                               redS[128 + r0] + redS[192 + r0]);
    const float inv2 = 1.0f / (redS[r0+8] + redS[64 + r0+8] +
                               redS[128 + r0+8] + redS[192 + r0+8]);

    // ---- Phase C: ctx = P @ K
    float oac[4][4];
    #pragma unroll
    for (int j = 0; j < 4; j++)
        #pragma unroll
        for (int i = 0; i < 4; i++) oac[j][i] = 0.0f;

    #pragma unroll 2
    for (int k = 0; k < 8; k++) {
        const uint32_t koff = k*32;
        uint32_t ah[4], al[4], b0h[4], b0l[4], b1h[4], b1l[4];
        ldsm_x4(ah, adrA + koff);
        ldsm_x4(al, adrA + koff + AHL);
        ldsm_x4(b0h, adrB0 + koff);
        ldsm_x4(b0l, adrB0 + koff + BHL);
        ldsm_x4(b1h, adrB1 + koff);
        ldsm_x4(b1l, adrB1 + koff + BHL);
        mma_bf16(oac[0], ah, b0h[0], b0h[1]);
        mma_bf16(oac[0], al, b0h[0], b0h[1]);
        mma_bf16(oac[0], ah, b0l[0], b0l[1]);
        mma_bf16(oac[1], ah, b0h[2], b0h[3]);
        mma_bf16(oac[1], al, b0h[2], b0h[3]);
        mma_bf16(oac[1], ah, b0l[2], b0l[3]);
        mma_bf16(oac[2], ah, b1h[0], b1h[1]);
        mma_bf16(oac[2], al, b1h[0], b1h[1]);
        mma_bf16(oac[2], ah, b1l[0], b1l[1]);
        mma_bf16(oac[3], ah, b1h[2], b1h[3]);
        mma_bf16(oac[3], al, b1h[2], b1h[3]);
        mma_bf16(oac[3], ah, b1l[2], b1l[3]);
    }

    // Epilogue
    #pragma unroll
    for (int j = 0; j < 4; j++) {
        const int cb = (nt0 + j)*8 + 2*tg;
        const int gr = rbase + r0;
        *(float2*)&out[n*HW_ + gr*128 + cb] =
            make_float2(oac[j][0]*inv1, oac[j][1]*inv1);
        *(float2*)&out[n*HW_ + (gr+8)*128 + cb] =
            make_float2(oac[j][2]*inv2, oac[j][3]*inv2);
    }
}

// ---------------------------------------------------------------------------
extern "C" void kernel_launch(void* const* d_in, const int* in_sizes, int n_in,
                              void* d_out, int out_size)
{
    const float* x  = (const float*)d_in[0];
    const float* e  = (const float*)d_in[1];
    const float* W1 = (const float*)d_in[2];
    const float* b1 = (const float*)d_in[3];
    const float* W2 = (const float*)d_in[4];
    const float* b2 = (const float*)d_in[5];
    const float* W3 = (const float*)d_in[6];
    const float* b3 = (const float*)d_in[7];
    float* out = (float*)d_out;

    const int smem1 = (4*64*LDW + 2*64*LDW1 + 2*128*LDW + 2*128*LDW1) * 4
                      + 3*64*4;
    cudaFuncSetAttribute(qvk_kernel, cudaFuncAttributeMaxDynamicSharedMemorySize, smem1);
    qvk_kernel<<<dim3(16, 16), 512, smem1>>>(x, e, W1, b1, W2, b2, W3, b3);

    const int smem2 = (2*64*LDP + 2*128*LDP) * 4 + 2*256*4;
    cudaFuncSetAttribute(attn_kernel, cudaFuncAttributeMaxDynamicSharedMemorySize, smem2);
    attn_kernel<<<NTOT*2, 512, smem2>>>(out);
}

// round 17
// speedup vs baseline: 1.3657x; 1.3657x over previous
#include <cuda_runtime.h>
#include <cstdint>

#define HW_ (128*128)
#define NTOT (16*64)
#define HWP (HW_/2)

__device__ uint2 g_Qp[NTOT * HWP];   // (hi,lo) bf16x2 pair per 2 pixels
__device__ uint2 g_Vp[NTOT * HWP];
__device__ float g_K [NTOT * HW_];

// ---- bf16x3 helpers ---------------------------------------------------------
__device__ __forceinline__ void mma_bf16(float c[4], const uint32_t a[4],
                                         const uint32_t b0, const uint32_t b1) {
    asm volatile(
        "mma.sync.aligned.m16n8k16.row.col.f32.bf16.bf16.f32 "
        "{%0,%1,%2,%3}, {%4,%5,%6,%7}, {%8,%9}, {%0,%1,%2,%3};"
        : "+f"(c[0]), "+f"(c[1]), "+f"(c[2]), "+f"(c[3])
        : "r"(a[0]), "r"(a[1]), "r"(a[2]), "r"(a[3]), "r"(b0), "r"(b1));
}

__device__ __forceinline__ void bf16x2_split(float x, float y,
                                             uint32_t& hi2, uint32_t& lo2) {
    uint32_t h;
    asm("cvt.rn.bf16x2.f32 %0, %1, %2;" : "=r"(h) : "f"(y), "f"(x));
    float xh = __uint_as_float(h << 16);
    float yh = __uint_as_float(h & 0xffff0000u);
    float xl = x - xh;
    float yl = y - yh;
    hi2 = h;
    asm("cvt.rn.bf16x2.f32 %0, %1, %2;" : "=r"(lo2) : "f"(yl), "f"(xl));
}

__device__ __forceinline__ void ldsm_x4(uint32_t r[4], uint32_t addr) {
    asm volatile(
        "ldmatrix.sync.aligned.m8n8.x4.shared.b16 {%0,%1,%2,%3}, [%4];"
        : "=r"(r[0]), "=r"(r[1]), "=r"(r[2]), "=r"(r[3]) : "r"(addr));
}

// ---------------------------------------------------------------------------
// Kernel 1: fused 1x1-conv projections (R15 structure; Q/V stored as uint2).
// ---------------------------------------------------------------------------
#define LDW  36
#define LDW1 12
#define WHL  (64*LDW*4)
#define W1HL (64*LDW1*4)
#define XHL  (128*LDW*4)
#define EHL  (128*LDW1*4)
#define NTILE 8

__global__ __launch_bounds__(512) void qvk_kernel(
    const float* __restrict__ x, const float* __restrict__ e,
    const float* __restrict__ W1, const float* __restrict__ b1,
    const float* __restrict__ W2, const float* __restrict__ b2,
    const float* __restrict__ W3, const float* __restrict__ b3)
{
    extern __shared__ uint32_t smu[];
    uint32_t* W2h = smu;
    uint32_t* W2l = W2h + 64*LDW;
    uint32_t* W3h = W2l + 64*LDW;
    uint32_t* W3l = W3h + 64*LDW;
    uint32_t* W1h = W3l + 64*LDW;
    uint32_t* W1l = W1h + 64*LDW1;
    uint32_t* Xph = W1l + 64*LDW1;
    uint32_t* Xpl = Xph + 128*LDW;
    uint32_t* Eph = Xpl + 128*LDW;
    uint32_t* Epl = Eph + 128*LDW1;
    float* b1s = (float*)(Epl + 128*LDW1);
    float* b2s = b1s + 64;
    float* b3s = b2s + 64;

    const int tid = threadIdx.x;
    const int b   = blockIdx.y;

    for (int idx = tid; idx < 2048; idx += 512) {
        int o = idx >> 5, p = idx & 31, c = 2*p;
        uint32_t h, l;
        bf16x2_split(W2[o*64 + c], W2[o*64 + c + 1], h, l);
        W2h[o*LDW + p] = h; W2l[o*LDW + p] = l;
        bf16x2_split(W3[o*64 + c], W3[o*64 + c + 1], h, l);
        W3h[o*LDW + p] = h; W3l[o*LDW + p] = l;
    }
    if (tid < 512) {
        int o = tid >> 3, p = tid & 7, c = 2*p;
        uint32_t h, l;
        bf16x2_split(W1[o*16 + c], W1[o*16 + c + 1], h, l);
        W1h[o*LDW1 + p] = h; W1l[o*LDW1 + p] = l;
    }
    if (tid < 64) { b1s[tid] = b1[tid]; b2s[tid] = b2[tid]; b3s[tid] = b3[tid]; }

    const int warp = tid >> 5;
    const int lane = tid & 31;
    const int g4 = lane >> 2;
    const int tg = lane & 3;
    const int wb = warp & 7;
    const int wh = warp >> 3;
    const int p0 = wb*16;
    const int o0 = wh*32;

    const int arow = ((lane >> 3) & 1)*8 + (lane & 7);
    const int acol = (lane >> 4)*4;
    const uint32_t adrW2_0 = (uint32_t)__cvta_generic_to_shared(
        &W2h[(o0 + arow)*LDW + acol]);
    const uint32_t adrW2_1 = (uint32_t)__cvta_generic_to_shared(
        &W2h[(o0 + 16 + arow)*LDW + acol]);
    const uint32_t adrW3_0 = (uint32_t)__cvta_generic_to_shared(
        &W3h[(o0 + arow)*LDW + acol]);
    const uint32_t adrW3_1 = (uint32_t)__cvta_generic_to_shared(
        &W3h[(o0 + 16 + arow)*LDW + acol]);
    const uint32_t adrW1_0 = (uint32_t)__cvta_generic_to_shared(
        &W1h[(o0 + arow)*LDW1 + acol]);
    const uint32_t adrW1_1 = (uint32_t)__cvta_generic_to_shared(
        &W1h[(o0 + 16 + arow)*LDW1 + acol]);
    const int btile = lane >> 3;
    const int brow  = p0 + (btile >> 1)*8 + (lane & 7);
    const int bcol  = (btile & 1)*4;
    const uint32_t adrX = (uint32_t)__cvta_generic_to_shared(
        &Xph[brow*LDW + bcol]);
    const uint32_t adrE = (uint32_t)__cvta_generic_to_shared(
        &Eph[brow*LDW1 + bcol]);

    for (int t = 0; t < NTILE; t++) {
        const int pblk = (blockIdx.x*NTILE + t) * 128;
        const float* xb = x + b*64*HW_ + pblk;
        const float* eb = e + b*16*HW_ + pblk;

        __syncthreads();
        for (int idx = tid; idx < 32*128; idx += 512) {
            int cp = idx >> 7, p = idx & 127;
            uint32_t h, l;
            bf16x2_split(xb[(2*cp)*HW_ + p], xb[(2*cp+1)*HW_ + p], h, l);
            Xph[p*LDW + cp] = h; Xpl[p*LDW + cp] = l;
        }
        for (int idx = tid; idx < 8*128; idx += 512) {
            int cp = idx >> 7, p = idx & 127;
            uint32_t h, l;
            bf16x2_split(eb[(2*cp)*HW_ + p], eb[(2*cp+1)*HW_ + p], h, l);
            Eph[p*LDW1 + cp] = h; Epl[p*LDW1 + cp] = l;
        }
        __syncthreads();

        float accV[2][2][4], accK[2][2][4], accQ[2][2][4];
        #pragma unroll
        for (int mt = 0; mt < 2; mt++) {
            int r = o0 + mt*16 + g4;
            float v0 = b2s[r], v1 = b2s[r+8];
            float k0 = b3s[r], k1 = b3s[r+8];
            float q0 = b1s[r], q1 = b1s[r+8];
            #pragma unroll
            for (int ntl = 0; ntl < 2; ntl++) {
                accV[mt][ntl][0] = v0; accV[mt][ntl][1] = v0;
                accV[mt][ntl][2] = v1; accV[mt][ntl][3] = v1;
                accK[mt][ntl][0] = k0; accK[mt][ntl][1] = k0;
                accK[mt][ntl][2] = k1; accK[mt][ntl][3] = k1;
                accQ[mt][ntl][0] = q0; accQ[mt][ntl][1] = q0;
                accQ[mt][ntl][2] = q1; accQ[mt][ntl][3] = q1;
            }
        }

        #pragma unroll
        for (int ks = 0; ks < 4; ks++) {
            const uint32_t ko = ks*32;
            uint32_t bxh[4], bxl[4];
            ldsm_x4(bxh, adrX + ko);
            ldsm_x4(bxl, adrX + ko + XHL);
            #pragma unroll
            for (int mt = 0; mt < 2; mt++) {
                const uint32_t aw2 = (mt ? adrW2_1 : adrW2_0) + ko;
                const uint32_t aw3 = (mt ? adrW3_1 : adrW3_0) + ko;
                uint32_t a2h[4], a2l[4], a3h[4], a3l[4];
                ldsm_x4(a2h, aw2);
                ldsm_x4(a2l, aw2 + WHL);
                ldsm_x4(a3h, aw3);
                ldsm_x4(a3l, aw3 + WHL);
                mma_bf16(accV[mt][0], a2h, bxh[0], bxh[1]);
                mma_bf16(accV[mt][0], a2l, bxh[0], bxh[1]);
                mma_bf16(accV[mt][0], a2h, bxl[0], bxl[1]);
                mma_bf16(accV[mt][1], a2h, bxh[2], bxh[3]);
                mma_bf16(accV[mt][1], a2l, bxh[2], bxh[3]);
                mma_bf16(accV[mt][1], a2h, bxl[2], bxl[3]);
                mma_bf16(accK[mt][0], a3h, bxh[0], bxh[1]);
                mma_bf16(accK[mt][0], a3l, bxh[0], bxh[1]);
                mma_bf16(accK[mt][0], a3h, bxl[0], bxl[1]);
                mma_bf16(accK[mt][1], a3h, bxh[2], bxh[3]);
                mma_bf16(accK[mt][1], a3l, bxh[2], bxh[3]);
                mma_bf16(accK[mt][1], a3h, bxl[2], bxl[3]);
            }
        }

        {
            uint32_t beh[4], bel[4];
            ldsm_x4(beh, adrE);
            ldsm_x4(bel, adrE + EHL);
            #pragma unroll
            for (int mt = 0; mt < 2; mt++) {
                const uint32_t aw1 = mt ? adrW1_1 : adrW1_0;
                uint32_t a1h[4], a1l[4];
                ldsm_x4(a1h, aw1);
                ldsm_x4(a1l, aw1 + W1HL);
                mma_bf16(accQ[mt][0], a1h, beh[0], beh[1]);
                mma_bf16(accQ[mt][0], a1l, beh[0], beh[1]);
                mma_bf16(accQ[mt][0], a1h, bel[0], bel[1]);
                mma_bf16(accQ[mt][1], a1h, beh[2], beh[3]);
                mma_bf16(accQ[mt][1], a1l, beh[2], beh[3]);
                mma_bf16(accQ[mt][1], a1h, bel[2], bel[3]);
            }
        }

        // Store: Q,V as interleaved uint2 (full 32B sectors per quad); K fp32
        #pragma unroll
        for (int mt = 0; mt < 2; mt++) {
            int r = o0 + mt*16 + g4;
            #pragma unroll
            for (int ntl = 0; ntl < 2; ntl++) {
                int pc = pblk + p0 + ntl*8 + 2*tg;
                int pq = pc >> 1;
                int n0 = b*64 + r, n1 = n0 + 8;
                uint32_t h, l;
                bf16x2_split(accQ[mt][ntl][0], accQ[mt][ntl][1], h, l);
                g_Qp[n0*HWP + pq] = make_uint2(h, l);
                bf16x2_split(accQ[mt][ntl][2], accQ[mt][ntl][3], h, l);
                g_Qp[n1*HWP + pq] = make_uint2(h, l);
                bf16x2_split(accV[mt][ntl][0], accV[mt][ntl][1], h, l);
                g_Vp[n0*HWP + pq] = make_uint2(h, l);
                bf16x2_split(accV[mt][ntl][2], accV[mt][ntl][3], h, l);
                g_Vp[n1*HWP + pq] = make_uint2(h, l);
                *(float2*)&g_K[n0*HW_ + pc] = make_float2(accK[mt][ntl][0], accK[mt][ntl][1]);
                *(float2*)&g_K[n1*HW_ + pc] = make_float2(accK[mt][ntl][2], accK[mt][ntl][3]);
            }
        }
    }
}

// ---------------------------------------------------------------------------
// Kernel 2: per-head attention (R14/R15 winner; staging reads uint2).
// ---------------------------------------------------------------------------
#define LDP 68
#define HL_OFF (128*LDP*4)

__global__ __launch_bounds__(1024) void attn_kernel(float* __restrict__ out)
{
    extern __shared__ uint32_t smu[];
    uint32_t* Ah = smu;
    uint32_t* Al = Ah + 128*LDP;
    uint32_t* Bh = Al + 128*LDP;
    uint32_t* Bl = Bh + 128*LDP;
    float* redM = (float*)(Bl + 128*LDP);
    float* redS = redM + 512;

    const int tid  = threadIdx.x;
    const int warp = tid >> 5;
    const int lane = tid & 31;
    const int wb   = warp & 7;
    const int wq   = warp >> 3;
    const int n    = blockIdx.x;
    const uint2* Qp = g_Qp + n*HWP;
    const uint2* Vp = g_Vp + n*HWP;
    const float* K  = g_K  + n*HW_;

    for (int idx = tid; idx < HWP; idx += 1024) {
        int r = idx >> 6, c = idx & 63;
        uint2 q = Qp[idx];
        uint2 v = Vp[idx];
        Ah[r*LDP + c] = q.x;
        Al[r*LDP + c] = q.y;
        Bh[r*LDP + c] = v.x;
        Bl[r*LDP + c] = v.y;
    }
    __syncthreads();

    const int g4 = lane >> 2;
    const int tg = lane & 3;
    const int r0 = wb*16 + g4;
    const int nt0 = wq*4;

    const int rowA = wb*16 + ((lane >> 3) & 1)*8 + (lane & 7);
    const int colA = (lane >> 4)*4;
    const uint32_t adrA =
        (uint32_t)__cvta_generic_to_shared(&Ah[rowA*LDP + colA]);
    const int tile  = lane >> 3;
    const int rowB0 = (nt0 + (tile >> 1))*8 + (lane & 7);
    const int rowB1 = (nt0 + 2 + (tile >> 1))*8 + (lane & 7);
    const int colB  = (tile & 1)*4;
    const uint32_t adrB0 =
        (uint32_t)__cvta_generic_to_shared(&Bh[rowB0*LDP + colB]);
    const uint32_t adrB1 =
        (uint32_t)__cvta_generic_to_shared(&Bh[rowB1*LDP + colB]);

    float acc[4][4];
    #pragma unroll
    for (int j = 0; j < 4; j++)
        #pragma unroll
        for (int i = 0; i < 4; i++) acc[j][i] = 0.0f;

    // ---- Phase A: S = Q @ V^T
    #pragma unroll 2
    for (int k = 0; k < 8; k++) {
        const uint32_t koff = k*32;
        uint32_t ah[4], al[4], b0h[4], b0l[4], b1h[4], b1l[4];
        ldsm_x4(ah, adrA + koff);
        ldsm_x4(al, adrA + koff + HL_OFF);
        ldsm_x4(b0h, adrB0 + koff);
        ldsm_x4(b0l, adrB0 + koff + HL_OFF);
        ldsm_x4(b1h, adrB1 + koff);
        ldsm_x4(b1l, adrB1 + koff + HL_OFF);
        mma_bf16(acc[0], ah, b0h[0], b0h[1]);
        mma_bf16(acc[0], al, b0h[0], b0h[1]);
        mma_bf16(acc[0], ah, b0l[0], b0l[1]);
        mma_bf16(acc[1], ah, b0h[2], b0h[3]);
        mma_bf16(acc[1], al, b0h[2], b0h[3]);
        mma_bf16(acc[1], ah, b0l[2], b0l[3]);
        mma_bf16(acc[2], ah, b1h[0], b1h[1]);
        mma_bf16(acc[2], al, b1h[0], b1h[1]);
        mma_bf16(acc[2], ah, b1l[0], b1l[1]);
        mma_bf16(acc[3], ah, b1h[2], b1h[3]);
        mma_bf16(acc[3], al, b1h[2], b1h[3]);
        mma_bf16(acc[3], ah, b1l[2], b1l[3]);
    }

    // ---- Softmax (4-warp row groups)
    float m1 = -1e30f, m2 = -1e30f;
    #pragma unroll
    for (int j = 0; j < 4; j++) {
        m1 = fmaxf(m1, fmaxf(acc[j][0], acc[j][1]));
        m2 = fmaxf(m2, fmaxf(acc[j][2], acc[j][3]));
    }
    #pragma unroll
    for (int off = 1; off < 4; off <<= 1) {
        m1 = fmaxf(m1, __shfl_xor_sync(0xFFFFFFFFu, m1, off));
        m2 = fmaxf(m2, __shfl_xor_sync(0xFFFFFFFFu, m2, off));
    }
    if (tg == 0) {
        redM[wq*128 + r0]     = m1;
        redM[wq*128 + r0 + 8] = m2;
    }
    __syncthreads();

    const float gm1 = fmaxf(fmaxf(redM[r0],       redM[128 + r0]),
                            fmaxf(redM[256 + r0], redM[384 + r0]));
    const float gm2 = fmaxf(fmaxf(redM[r0+8],       redM[128 + r0+8]),
                            fmaxf(redM[256 + r0+8], redM[384 + r0+8]));

    float s1 = 0.0f, s2 = 0.0f;
    #pragma unroll
    for (int j = 0; j < 4; j++) {
        acc[j][0] = __expf(acc[j][0] - gm1);
        acc[j][1] = __expf(acc[j][1] - gm1);
        acc[j][2] = __expf(acc[j][2] - gm2);
        acc[j][3] = __expf(acc[j][3] - gm2);
        s1 += acc[j][0] + acc[j][1];
        s2 += acc[j][2] + acc[j][3];
    }
    #pragma unroll
    for (int off = 1; off < 4; off <<= 1) {
        s1 += __shfl_xor_sync(0xFFFFFFFFu, s1, off);
        s2 += __shfl_xor_sync(0xFFFFFFFFu, s2, off);
    }
    if (tg == 0) {
        redS[wq*128 + r0]     = s1;
        redS[wq*128 + r0 + 8] = s2;
    }

    // Store P split into A-buf
    #pragma unroll
    for (int j = 0; j < 4; j++) {
        const int pb = (nt0 + j)*4 + tg;
        uint32_t h, l;
        bf16x2_split(acc[j][0], acc[j][1], h, l);
        Ah[r0*LDP + pb] = h; Al[r0*LDP + pb] = l;
        bf16x2_split(acc[j][2], acc[j][3], h, l);
        Ah[(r0+8)*LDP + pb] = h; Al[(r0+8)*LDP + pb] = l;
    }
    // Stage K transposed + g-pair packed: Ktp[w][gp]
    for (int idx = tid; idx < 64*128; idx += 1024) {
        int gp = idx >> 7, w = idx & 127;
        uint32_t h, l;
        bf16x2_split(K[(2*gp)*128 + w], K[(2*gp+1)*128 + w], h, l);
        Bh[w*LDP + gp] = h; Bl[w*LDP + gp] = l;
    }
    __syncthreads();

    const float inv1 = 1.0f / (redS[r0] + redS[128 + r0] +
                               redS[256 + r0] + redS[384 + r0]);
    const float inv2 = 1.0f / (redS[r0+8] + redS[128 + r0+8] +
                               redS[256 + r0+8] + redS[384 + r0+8]);

    // ---- Phase C: ctx = P @ K
    float oac[4][4];
    #pragma unroll
    for (int j = 0; j < 4; j++)
        #pragma unroll
        for (int i = 0; i < 4; i++) oac[j][i] = 0.0f;

    #pragma unroll 2
    for (int k = 0; k < 8; k++) {
        const uint32_t koff = k*32;
        uint32_t ah[4], al[4], b0h[4], b0l[4], b1h[4], b1l[4];
        ldsm_x4(ah, adrA + koff);
        ldsm_x4(al, adrA + koff + HL_OFF);
        ldsm_x4(b0h, adrB0 + koff);
        ldsm_x4(b0l, adrB0 + koff + HL_OFF);
        ldsm_x4(b1h, adrB1 + koff);
        ldsm_x4(b1l, adrB1 + koff + HL_OFF);
        mma_bf16(oac[0], ah, b0h[0], b0h[1]);
        mma_bf16(oac[0], al, b0h[0], b0h[1]);
        mma_bf16(oac[0], ah, b0l[0], b0l[1]);
        mma_bf16(oac[1], ah, b0h[2], b0h[3]);
        mma_bf16(oac[1], al, b0h[2], b0h[3]);
        mma_bf16(oac[1], ah, b0l[2], b0l[3]);
        mma_bf16(oac[2], ah, b1h[0], b1h[1]);
        mma_bf16(oac[2], al, b1h[0], b1h[1]);
        mma_bf16(oac[2], ah, b1l[0], b1l[1]);
        mma_bf16(oac[3], ah, b1h[2], b1h[3]);
        mma_bf16(oac[3], al, b1h[2], b1h[3]);
        mma_bf16(oac[3], ah, b1l[2], b1l[3]);
    }

    // Epilogue
    #pragma unroll
    for (int j = 0; j < 4; j++) {
        const int cb = (nt0 + j)*8 + 2*tg;
        *(float2*)&out[n*HW_ + r0*128 + cb] =
            make_float2(oac[j][0]*inv1, oac[j][1]*inv1);
        *(float2*)&out[n*HW_ + (r0+8)*128 + cb] =
            make_float2(oac[j][2]*inv2, oac[j][3]*inv2);
    }
}

// ---------------------------------------------------------------------------
extern "C" void kernel_launch(void* const* d_in, const int* in_sizes, int n_in,
                              void* d_out, int out_size)
{
    const float* x  = (const float*)d_in[0];
    const float* e  = (const float*)d_in[1];
    const float* W1 = (const float*)d_in[2];
    const float* b1 = (const float*)d_in[3];
    const float* W2 = (const float*)d_in[4];
    const float* b2 = (const float*)d_in[5];
    const float* W3 = (const float*)d_in[6];
    const float* b3 = (const float*)d_in[7];
    float* out = (float*)d_out;

    const int smem1 = (4*64*LDW + 2*64*LDW1 + 2*128*LDW + 2*128*LDW1) * 4
                      + 3*64*4;
    cudaFuncSetAttribute(qvk_kernel, cudaFuncAttributeMaxDynamicSharedMemorySize, smem1);
    qvk_kernel<<<dim3(16, 16), 512, smem1>>>(x, e, W1, b1, W2, b2, W3, b3);

    const int smem2 = (4*128*LDP) * 4 + 2*512*4;
    cudaFuncSetAttribute(attn_kernel, cudaFuncAttributeMaxDynamicSharedMemorySize, smem2);
    attn_kernel<<<NTOT, 1024, smem2>>>(out);
}